// round 3
// baseline (speedup 1.0000x reference)
#include <cuda_runtime.h>
#include <math.h>

#define EPSF 1e-7f
#define MAX_TANHF (1.0f - 1e-6f)

constexpr int F = 128;
constexpr int NMAX = 8192;

// Scratch (no allocation allowed anywhere)
__device__ float g_V [NMAX * F];      // log0(h)
__device__ float g_C [NMAX * 2 * F];  // log0([x ; neigh])

typedef unsigned long long ull;

__device__ __forceinline__ float warp_sum(float v) {
    v += __shfl_xor_sync(0xffffffffu, v, 16);
    v += __shfl_xor_sync(0xffffffffu, v, 8);
    v += __shfl_xor_sync(0xffffffffu, v, 4);
    v += __shfl_xor_sync(0xffffffffu, v, 2);
    v += __shfl_xor_sync(0xffffffffu, v, 1);
    return v;
}

__device__ __forceinline__ float dot4(float4 a, float4 b) {
    return a.x * b.x + a.y * b.y + a.z * b.z + a.w * b.w;
}

// Packed fp32x2 FMA (SASS FFMA2) — 2x fp32 FMA per issue, fp32-exact.
__device__ __forceinline__ void ffma2(ull& d, ull a, ull b) {
    asm("fma.rn.f32x2 %0, %1, %2, %0;" : "+l"(d) : "l"(a), "l"(b));
}
__device__ __forceinline__ ull pack2(float lo, float hi) {
    ull r; asm("mov.b64 %0, {%1, %2};" : "=l"(r) : "f"(lo), "f"(hi)); return r;
}
__device__ __forceinline__ float2 unpack2(ull v) {
    float2 r; asm("mov.b64 {%0, %1}, %2;" : "=f"(r.x), "=f"(r.y) : "l"(v)); return r;
}

// GEMM geometry: 32-row tile, 256 threads (8 warps), thread = 4 rows x 4 cols.
// A stored transposed in smem as row-PAIRS: Ap[k*SA + pair], SA padded.
constexpr int SA = 17;                       // ull stride per k (16 pairs + pad)
constexpr int BS_BYTES = 128 * 128 * 4;      // 64 KB B chunk
constexpr int AP_BYTES = 128 * SA * 8;       // 17408 B
constexpr int SMEM_G = BS_BYTES + AP_BYTES + 256;

// ---------------------------------------------------------------------------
// Stage 1: V = log0( h_add( exp0( log0(x) @ embed ), ebias ) )
// ---------------------------------------------------------------------------
__global__ void __launch_bounds__(256, 2)
k_g128(const float* __restrict__ x, const float* __restrict__ B,
       const float* __restrict__ ebias, float* __restrict__ V) {
    extern __shared__ char smraw[];
    float* Bs  = (float*)smraw;
    ull*   Ap  = (ull*)(smraw + BS_BYTES);
    float* srow = (float*)(smraw + BS_BYTES + AP_BYTES);

    int tid = threadIdx.x, lane = tid & 31, w = tid >> 5;
    int row0 = blockIdx.x * 32;
    const float4* X4 = (const float4*)x;

    // phase 0: per-row log0 scale factors (warp w owns rows 4w..4w+3)
#pragma unroll
    for (int r = 0; r < 4; r++) {
        int row = w * 4 + r;
        float4 xv = X4[(size_t)(row0 + row) * 32 + lane];
        float n2 = warp_sum(dot4(xv, xv));
        float n = fmaxf(sqrtf(n2), EPSF);
        float sc = atanhf(fminf(n, MAX_TANHF)) / n;
        if (lane == 0) srow[row] = sc;
    }
    // B -> smem
    {
        const float4* B4 = (const float4*)B;
        float4* Bs4 = (float4*)Bs;
        for (int i = tid; i < 4096; i += 256) Bs4[i] = B4[i];
    }
    __syncthreads();

    // phase 1: scaled transpose into row-pair-packed Ap
    for (int i = tid; i < 16 * 32; i += 256) {
        int pr = i >> 5, cg = i & 31;
        float s0 = srow[2 * pr], s1 = srow[2 * pr + 1];
        float4 v0 = X4[(size_t)(row0 + 2 * pr) * 32 + cg];
        float4 v1 = X4[(size_t)(row0 + 2 * pr + 1) * 32 + cg];
        Ap[(cg * 4 + 0) * SA + pr] = pack2(v0.x * s0, v1.x * s1);
        Ap[(cg * 4 + 1) * SA + pr] = pack2(v0.y * s0, v1.y * s1);
        Ap[(cg * 4 + 2) * SA + pr] = pack2(v0.z * s0, v1.z * s1);
        Ap[(cg * 4 + 3) * SA + pr] = pack2(v0.w * s0, v1.w * s1);
    }
    __syncthreads();

    int c4 = lane * 4;
    int pb = w * 2;  // row-pair base (rows 4w..4w+3)

    ull acc[2][4];
#pragma unroll
    for (int p = 0; p < 2; p++)
#pragma unroll
        for (int c = 0; c < 4; c++) acc[p][c] = 0ull;

#pragma unroll 4
    for (int k = 0; k < 128; k++) {
        float4 b4 = *(const float4*)(Bs + k * 128 + c4);
        ull bd0 = pack2(b4.x, b4.x), bd1 = pack2(b4.y, b4.y);
        ull bd2 = pack2(b4.z, b4.z), bd3 = pack2(b4.w, b4.w);
        const ull* ap = Ap + k * SA + pb;
        ull a0 = ap[0], a1 = ap[1];
        ffma2(acc[0][0], a0, bd0); ffma2(acc[0][1], a0, bd1);
        ffma2(acc[0][2], a0, bd2); ffma2(acc[0][3], a0, bd3);
        ffma2(acc[1][0], a1, bd0); ffma2(acc[1][1], a1, bd1);
        ffma2(acc[1][2], a1, bd2); ffma2(acc[1][3], a1, bd3);
    }

    // epilogue: exp0 -> h_add(ebias) -> log0
    float4 bb = *(const float4*)(ebias + c4);
    float y2 = warp_sum(dot4(bb, bb));
    float4* V4 = (float4*)V;
#pragma unroll
    for (int p = 0; p < 2; p++) {
        float2 u0 = unpack2(acc[p][0]), u1 = unpack2(acc[p][1]);
        float2 u2 = unpack2(acc[p][2]), u3 = unpack2(acc[p][3]);
        float4 ur[2] = {make_float4(u0.x, u1.x, u2.x, u3.x),
                        make_float4(u0.y, u1.y, u2.y, u3.y)};
#pragma unroll
        for (int q = 0; q < 2; q++) {
            float4 u = ur[q];
            int row = row0 + w * 4 + 2 * p + q;
            float ne2 = warp_sum(dot4(u, u));
            float ne = fmaxf(sqrtf(ne2), EPSF);
            float sc = tanhf(ne) / ne;
            float4 h = make_float4(u.x * sc, u.y * sc, u.z * sc, u.w * sc);
            float xy = warp_sum(dot4(h, bb));
            float x2 = sc * sc * ne2;
            float c1 = 1.f + 2.f * xy + y2;
            float c2 = 1.f - x2;
            float inv_den = 1.f / fmaxf(1.f + 2.f * xy + x2 * y2, EPSF);
            float4 rr = make_float4((c1 * h.x + c2 * bb.x) * inv_den,
                                    (c1 * h.y + c2 * bb.y) * inv_den,
                                    (c1 * h.z + c2 * bb.z) * inv_den,
                                    (c1 * h.w + c2 * bb.w) * inv_den);
            float nr2 = warp_sum(dot4(rr, rr));
            float nr = fmaxf(sqrtf(nr2), EPSF);
            float s = atanhf(fminf(nr, MAX_TANHF)) / nr;
            V4[(size_t)row * 32 + lane] =
                make_float4(rr.x * s, rr.y * s, rr.z * s, rr.w * s);
        }
    }
}

// ---------------------------------------------------------------------------
// Stage 2: C = log0([x ; exp0(adj @ V)]) — warp/row, 4-deep stream pipeline
// ---------------------------------------------------------------------------
__global__ void k_spmm_fused(const float* __restrict__ adj,
                             const float* __restrict__ x, int N) {
    int warp = (blockIdx.x * blockDim.x + threadIdx.x) >> 5;
    int lane = threadIdx.x & 31;
    if (warp >= N) return;

    const float4* V4 = (const float4*)g_V;
    const float4* arow = (const float4*)(adj + (size_t)warp * N);
    float4 acc = make_float4(0.f, 0.f, 0.f, 0.f);

    int nq = N / 4;  // 2048
    float4 buf[4];
#pragma unroll
    for (int d = 0; d < 4; d++) buf[d] = __ldcs(arow + d * 32 + lane);

    for (int jbo = 0; jbo < nq; jbo += 128) {
#pragma unroll
        for (int d = 0; d < 4; d++) {
            float4 cur = buf[d];
            int nx = jbo + 128 + d * 32;
            buf[d] = (nx < nq) ? __ldcs(arow + nx + lane)
                               : make_float4(0.f, 0.f, 0.f, 0.f);
            int jb = jbo + d * 32;
#pragma unroll
            for (int c = 0; c < 4; c++) {
                float av = (c == 0) ? cur.x : (c == 1) ? cur.y
                            : (c == 2) ? cur.z : cur.w;
                unsigned m = __ballot_sync(0xffffffffu, av != 0.0f);
                while (m) {
                    int b = __ffs(m) - 1;
                    m &= m - 1;
                    float aval = __shfl_sync(0xffffffffu, av, b);
                    int j = (jb + b) * 4 + c;
                    float4 v = V4[(size_t)j * 32 + lane];
                    acc.x += aval * v.x;
                    acc.y += aval * v.y;
                    acc.z += aval * v.z;
                    acc.w += aval * v.w;
                }
            }
        }
    }

    float nn2 = warp_sum(dot4(acc, acc));
    float nn = fmaxf(sqrtf(nn2), EPSF);
    float e = tanhf(nn) / nn;
    float4 ng = make_float4(acc.x * e, acc.y * e, acc.z * e, acc.w * e);

    float4 xv = ((const float4*)x)[(size_t)warp * 32 + lane];
    float nx2 = warp_sum(dot4(xv, xv));
    float ng2 = e * e * nn2;
    float nc = fmaxf(sqrtf(nx2 + ng2), EPSF);
    float s = atanhf(fminf(nc, MAX_TANHF)) / nc;

    float4* C4 = (float4*)g_C;
    C4[(size_t)warp * 64 + lane]      = make_float4(xv.x * s, xv.y * s, xv.z * s, xv.w * s);
    C4[(size_t)warp * 64 + 32 + lane] = make_float4(ng.x * s, ng.y * s, ng.z * s, ng.w * s);
}

// ---------------------------------------------------------------------------
// Stage 3: out = h_add( exp0( C @ layer ), lbias ), K=256 via two 128-chunks
// ---------------------------------------------------------------------------
__global__ void __launch_bounds__(256, 2)
k_g256(const float* __restrict__ A, const float* __restrict__ B,
       const float* __restrict__ lbias, float* __restrict__ out) {
    extern __shared__ char smraw[];
    float* Bs = (float*)smraw;
    ull*   Ap = (ull*)(smraw + BS_BYTES);

    int tid = threadIdx.x, lane = tid & 31, w = tid >> 5;
    int row0 = blockIdx.x * 32;
    int c4 = lane * 4;
    int pb = w * 2;

    const float4* A4 = (const float4*)A;  // row stride 64 float4 (256 floats)

    ull acc[2][4];
#pragma unroll
    for (int p = 0; p < 2; p++)
#pragma unroll
        for (int c = 0; c < 4; c++) acc[p][c] = 0ull;

    for (int kc = 0; kc < 2; kc++) {
        {
            const float4* B4 = (const float4*)(B + kc * 128 * 128);
            float4* Bs4 = (float4*)Bs;
            for (int i = tid; i < 4096; i += 256) Bs4[i] = B4[i];
        }
        for (int i = tid; i < 16 * 32; i += 256) {
            int pr = i >> 5, cg = i & 31;
            float4 v0 = A4[(size_t)(row0 + 2 * pr) * 64 + kc * 32 + cg];
            float4 v1 = A4[(size_t)(row0 + 2 * pr + 1) * 64 + kc * 32 + cg];
            Ap[(cg * 4 + 0) * SA + pr] = pack2(v0.x, v1.x);
            Ap[(cg * 4 + 1) * SA + pr] = pack2(v0.y, v1.y);
            Ap[(cg * 4 + 2) * SA + pr] = pack2(v0.z, v1.z);
            Ap[(cg * 4 + 3) * SA + pr] = pack2(v0.w, v1.w);
        }
        __syncthreads();

#pragma unroll 4
        for (int k = 0; k < 128; k++) {
            float4 b4 = *(const float4*)(Bs + k * 128 + c4);
            ull bd0 = pack2(b4.x, b4.x), bd1 = pack2(b4.y, b4.y);
            ull bd2 = pack2(b4.z, b4.z), bd3 = pack2(b4.w, b4.w);
            const ull* ap = Ap + k * SA + pb;
            ull a0 = ap[0], a1 = ap[1];
            ffma2(acc[0][0], a0, bd0); ffma2(acc[0][1], a0, bd1);
            ffma2(acc[0][2], a0, bd2); ffma2(acc[0][3], a0, bd3);
            ffma2(acc[1][0], a1, bd0); ffma2(acc[1][1], a1, bd1);
            ffma2(acc[1][2], a1, bd2); ffma2(acc[1][3], a1, bd3);
        }
        __syncthreads();
    }

    // epilogue: exp0 -> h_add(lbias)
    float4 bb = *(const float4*)(lbias + c4);
    float y2 = warp_sum(dot4(bb, bb));
    float4* O4 = (float4*)out;
#pragma unroll
    for (int p = 0; p < 2; p++) {
        float2 u0 = unpack2(acc[p][0]), u1 = unpack2(acc[p][1]);
        float2 u2 = unpack2(acc[p][2]), u3 = unpack2(acc[p][3]);
        float4 ur[2] = {make_float4(u0.x, u1.x, u2.x, u3.x),
                        make_float4(u0.y, u1.y, u2.y, u3.y)};
#pragma unroll
        for (int q = 0; q < 2; q++) {
            float4 u = ur[q];
            int row = row0 + w * 4 + 2 * p + q;
            float ne2 = warp_sum(dot4(u, u));
            float ne = fmaxf(sqrtf(ne2), EPSF);
            float sc = tanhf(ne) / ne;
            float4 h = make_float4(u.x * sc, u.y * sc, u.z * sc, u.w * sc);
            float xy = warp_sum(dot4(h, bb));
            float x2 = sc * sc * ne2;
            float c1 = 1.f + 2.f * xy + y2;
            float c2 = 1.f - x2;
            float inv_den = 1.f / fmaxf(1.f + 2.f * xy + x2 * y2, EPSF);
            O4[(size_t)row * 32 + lane] =
                make_float4((c1 * h.x + c2 * bb.x) * inv_den,
                            (c1 * h.y + c2 * bb.y) * inv_den,
                            (c1 * h.z + c2 * bb.z) * inv_den,
                            (c1 * h.w + c2 * bb.w) * inv_den);
        }
    }
}

// ---------------------------------------------------------------------------
extern "C" void kernel_launch(void* const* d_in, const int* in_sizes, int n_in,
                              void* d_out, int out_size) {
    const float* x     = (const float*)d_in[0];
    const float* adj   = (const float*)d_in[1];
    const float* embed = (const float*)d_in[2];
    const float* layer = (const float*)d_in[3];
    const float* ebias = (const float*)d_in[4];
    const float* lbias = (const float*)d_in[5];
    float* out = (float*)d_out;

    int N = in_sizes[0] / F;  // 8192

    float *pV, *pC;
    cudaGetSymbolAddress((void**)&pV, g_V);
    cudaGetSymbolAddress((void**)&pC, g_C);

    cudaFuncSetAttribute(k_g128, cudaFuncAttributeMaxDynamicSharedMemorySize, SMEM_G);
    cudaFuncSetAttribute(k_g256, cudaFuncAttributeMaxDynamicSharedMemorySize, SMEM_G);

    k_g128<<<N / 32, 256, SMEM_G>>>(x, embed, ebias, pV);
    k_spmm_fused<<<N / 8, 256>>>(adj, x, N);
    k_g256<<<N / 32, 256, SMEM_G>>>(pC, layer, lbias, out);
}